// round 4
// baseline (speedup 1.0000x reference)
#include <cuda_runtime.h>

// SmartDoorClassifier — LIF degeneracy (alpha = exp(-200) == 0.0f in fp32):
// spiking LIF == floor(relu(.)), readout LIF == identity.
// conv1(2x2,s2)->fr->pool2 -> conv2(3x3,p1)->fr->pool2 -> conv3(3x3,p1)->fr->pool2 -> FC.
// conv1: FFMA2 packed along input channels. conv2/conv3: FFMA2 packed along
// input-channel pairs with ic-interleaved float2 activation storage.

#define SW2  0                // 576 floats: conv2 w packed [oc][icp][9] float2
#define SW3  576              // 576: conv3 likewise
#define W1P  1152             // 64: conv1 w packed [oc][dydx] float2 (ch pair)
#define P1   1216             // 4 icp planes x 34 rows x 48 elems x2 = 13056
#define P2   14272            // 4 x 18 x 20 x2 = 2880
#define P3   17152            // 512
#define RD   17664            // 16
#define TOT  17680            // floats = 70720 bytes

#define RS1  96               // p1 row stride (floats) = 48 elems
#define FPS1 3264             // p1 plane stride (floats)
#define RS2  40               // p2 row stride (floats) = 20 elems
#define FPS2 720              // p2 plane stride (floats)

typedef unsigned long long u64;

__device__ __forceinline__ void fma2(u64& d, u64 a, u64 b) {
    asm("fma.rn.f32x2 %0, %1, %2, %0;" : "+l"(d) : "l"(a), "l"(b));
}
__device__ __forceinline__ u64 pk(float lo, float hi) {
    u64 d; asm("mov.b64 %0, {%1, %2};" : "=l"(d) : "f"(lo), "f"(hi)); return d;
}
__device__ __forceinline__ void upk(u64 d, float& lo, float& hi) {
    asm("mov.b64 {%0, %1}, %2;" : "=f"(lo), "=f"(hi) : "l"(d));
}

__global__ __launch_bounds__(256, 3)
void snn_fused_kernel(const float* __restrict__ x,
                      const float* __restrict__ w1,
                      const float* __restrict__ w2,
                      const float* __restrict__ w3,
                      const float* __restrict__ wfc,
                      float* __restrict__ out)
{
    extern __shared__ float sm[];
    const int t    = threadIdx.x;
    const int n    = blockIdx.x;
    const int lane = t & 31;

    // ---- init: packed weights + zero p1/p2 (halo must be 0) -------------
    for (int i = t; i < 288; i += 256) {
        const int oc = i / 36, icp = (i % 36) / 9, q = i % 9;
        const int b = oc * 72 + icp * 18 + q;
        ((float2*)(sm + SW2))[i] = make_float2(w2[b], w2[b + 9]);
        ((float2*)(sm + SW3))[i] = make_float2(w3[b], w3[b + 9]);
    }
    if (t < 32) {  // conv1: {ch0, ch1} pairs per (oc, dydx)
        const int oc = t >> 2, dydx = t & 3;
        ((float2*)(sm + W1P))[t] = make_float2(w1[oc * 8 + dydx], w1[oc * 8 + 4 + dydx]);
    }
    {
        float4 z = make_float4(0.f, 0.f, 0.f, 0.f);
        float4* zp = (float4*)(sm + P1);
        for (int i = t; i < (13056 + 2880) / 4; i += 256) zp[i] = z;
    }
    __syncthreads();

    // ------------------------------------------------------------------
    // Stage A: conv1 + floor(relu) + pool2 -> p1 (icp-packed, swizzled)
    // Thread = pooled position; FFMA2 packed along input channels.
    // ------------------------------------------------------------------
    {
        const float* xn = x + (size_t)n * 32768;
        const int px = lane, py0 = t >> 5;
#pragma unroll 1
        for (int k = 0; k < 4; k++) {
            const int py = py0 + 8 * k;
            u64 P[16];                       // {ch0, ch1} per patch elem
#pragma unroll
            for (int r = 0; r < 4; r++) {
                float4 a = *(const float4*)(xn + (4 * py + r) * 128 + 4 * px);
                float4 b = *(const float4*)(xn + 16384 + (4 * py + r) * 128 + 4 * px);
                P[r*4+0] = pk(a.x, b.x); P[r*4+1] = pk(a.y, b.y);
                P[r*4+2] = pk(a.z, b.z); P[r*4+3] = pk(a.w, b.w);
            }
            float o[8];
#pragma unroll
            for (int oc = 0; oc < 8; oc++) {
                ulonglong2 wv = *(const ulonglong2*)(sm + W1P + oc * 8);
                u64 acc[4];
#pragma unroll
                for (int i = 0; i < 2; i++)
#pragma unroll
                for (int j = 0; j < 2; j++) {
                    u64 c = 0ull;
                    fma2(c, P[(2*i+0)*4 + 2*j+0], wv.x);          // dy0 dx0
                    fma2(c, P[(2*i+0)*4 + 2*j+1], ((u64*)&wv)[0] >> 0 ? 0 : 0), c = c; // placeholder removed below
                    acc[i*2+j] = c;
                }
                // (loop rewritten below without placeholder)
                (void)acc;
                float mx = -3.0e38f;
#pragma unroll
                for (int i = 0; i < 2; i++)
#pragma unroll
                for (int j = 0; j < 2; j++) {
                    u64 c = 0ull;
                    const u64 w00 = wv.x, w01 = wv.y;
                    ulonglong2 wv2 = *(const ulonglong2*)(sm + W1P + oc * 8 + 4);
                    fma2(c, P[(2*i+0)*4 + 2*j+0], w00);
                    fma2(c, P[(2*i+0)*4 + 2*j+1], w01);
                    fma2(c, P[(2*i+1)*4 + 2*j+0], wv2.x);
                    fma2(c, P[(2*i+1)*4 + 2*j+1], wv2.y);
                    float lo, hi; upk(c, lo, hi);
                    mx = fmaxf(mx, lo + hi);
                }
                o[oc] = floorf(fmaxf(mx, 0.f));
            }
            const int row = py + 1, col = px + 1;
            const int key = (row >> 1) & 7;
            const int chunk = col >> 1;
            const int phys = (chunk & ~7) | ((chunk & 7) ^ key);
            const int eoff = row * RS1 + (phys * 2 + (col & 1)) * 2;
#pragma unroll
            for (int icp = 0; icp < 4; icp++)
                *(float2*)(sm + P1 + icp * FPS1 + eoff) = make_float2(o[2*icp], o[2*icp+1]);
        }
    }
    __syncthreads();

    // ------------------------------------------------------------------
    // Stage B: conv2 + floor(relu) + pool2 -> p2 (icp-packed)
    // warp = oc; lane = half*16 + py2. Four 2-pooled-col passes; addresses
    // precomputed per pass, ic loop unrolled -> pure LDS+FFMA2 inner.
    // ------------------------------------------------------------------
    {
        const int oc  = t >> 5;
        const int py2 = lane & 15, half = lane >> 4;
        const int key0 = py2 & 7, key1 = (py2 + 1) & 7;
        const float* wb = sm + SW2 + oc * 72;
        const int row2 = py2 + 1;
        const int key2 = (row2 >> 1) & 1;
#pragma unroll 1
        for (int p = 0; p < 4; p++) {
            const int cbase = 8 * half + 2 * p;
            const float* aptr[4][3];
#pragma unroll
            for (int r = 0; r < 4; r++) {
                const int key = (r < 2) ? key0 : key1;
                const int rbase = (2 * py2 + r) * RS1;
#pragma unroll
                for (int k = 0; k < 3; k++) {
                    const int c = cbase + k;
                    const int phys = (c & ~7) | ((c & 7) ^ key);
                    aptr[r][k] = sm + P1 + rbase + phys * 4;
                }
            }
            u64 acc[8];
#pragma unroll
            for (int i = 0; i < 8; i++) acc[i] = 0ull;
#pragma unroll
            for (int icp = 0; icp < 4; icp++) {
                u64 w[9];
#pragma unroll
                for (int q = 0; q < 9; q++)
                    w[q] = *(const u64*)(wb + (icp * 9 + q) * 2);
#pragma unroll
                for (int r = 0; r < 4; r++) {
                    u64 e[6];
#pragma unroll
                    for (int k = 0; k < 3; k++) {
                        ulonglong2 v = *(const ulonglong2*)(aptr[r][k] + icp * FPS1);
                        e[2*k] = v.x; e[2*k+1] = v.y;
                    }
#pragma unroll
                    for (int ky = 0; ky < 3; ky++) {
                        const int i = r - ky;
                        if (i >= 0 && i <= 1) {
#pragma unroll
                            for (int jp = 0; jp < 2; jp++)
#pragma unroll
                            for (int jj = 0; jj < 2; jj++)
#pragma unroll
                            for (int kx = 0; kx < 3; kx++)
                                fma2(acc[jp*4 + i*2 + jj], e[2*jp + jj + kx], w[ky*3 + kx]);
                        }
                    }
                }
            }
#pragma unroll
            for (int jp = 0; jp < 2; jp++) {
                float s[4];
#pragma unroll
                for (int c = 0; c < 4; c++) {
                    float lo, hi; upk(acc[jp*4 + c], lo, hi); s[c] = lo + hi;
                }
                float mx = fmaxf(fmaxf(s[0], s[1]), fmaxf(s[2], s[3]));
                const int e2 = 8 * half + 2 * p + jp + 1;
                const int pe = (((e2 >> 1) ^ key2) << 1) | (e2 & 1);
                sm[P2 + (oc >> 1) * FPS2 + row2 * RS2 + pe * 2 + (oc & 1)]
                    = floorf(fmaxf(mx, 0.f));
            }
        }
    }
    __syncthreads();

    // ------------------------------------------------------------------
    // Stage C: conv3 + floor(relu) + pool2 -> p3[8][8][8]
    // warp = oc; lane = py3*4 + q (cols 2q, 2q+1). Precomputed addresses.
    // ------------------------------------------------------------------
    {
        const int oc  = t >> 5;
        const int py3 = lane >> 2, q = lane & 3;
        const float* wb = sm + SW3 + oc * 72;
        const float* cptr[4][3];
#pragma unroll
        for (int r = 0; r < 4; r++) {
            const int row = 2 * py3 + r;
            const int key = (row >> 1) & 1;
#pragma unroll
            for (int k = 0; k < 3; k++)
                cptr[r][k] = sm + P2 + row * RS2 + ((2 * q + k) ^ key) * 4;
        }
        u64 acc[8];
#pragma unroll
        for (int i = 0; i < 8; i++) acc[i] = 0ull;
#pragma unroll
        for (int icp = 0; icp < 4; icp++) {
            u64 w[9];
#pragma unroll
            for (int p = 0; p < 9; p++)
                w[p] = *(const u64*)(wb + (icp * 9 + p) * 2);
#pragma unroll
            for (int r = 0; r < 4; r++) {
                u64 e[6];
#pragma unroll
                for (int k = 0; k < 3; k++) {
                    ulonglong2 v = *(const ulonglong2*)(cptr[r][k] + icp * FPS2);
                    e[2*k] = v.x; e[2*k+1] = v.y;
                }
#pragma unroll
                for (int ky = 0; ky < 3; ky++) {
                    const int i = r - ky;
                    if (i >= 0 && i <= 1) {
#pragma unroll
                        for (int j = 0; j < 2; j++)
#pragma unroll
                        for (int jj = 0; jj < 2; jj++)
#pragma unroll
                        for (int kx = 0; kx < 3; kx++)
                            fma2(acc[j*4 + i*2 + jj], e[2*j + jj + kx], w[ky*3 + kx]);
                    }
                }
            }
        }
#pragma unroll
        for (int j = 0; j < 2; j++) {
            float s[4];
#pragma unroll
            for (int c = 0; c < 4; c++) {
                float lo, hi; upk(acc[j*4 + c], lo, hi); s[c] = lo + hi;
            }
            float mx = fmaxf(fmaxf(s[0], s[1]), fmaxf(s[2], s[3]));
            sm[P3 + oc * 64 + py3 * 8 + 2 * q + j] = floorf(fmaxf(mx, 0.f));
        }
    }
    __syncthreads();

    // ------------------------------------------------------------------
    // Stage D: FC 512 -> 2 (readout LIF = identity); wfc via L2 (__ldg)
    // ------------------------------------------------------------------
    {
        const int oc = t >> 5;
        float a0 = 0.f, a1 = 0.f;
        for (int i = t; i < 512; i += 256) {
            const float v = sm[P3 + i];
            a0 = fmaf(v, __ldg(&wfc[i]),       a0);
            a1 = fmaf(v, __ldg(&wfc[512 + i]), a1);
        }
#pragma unroll
        for (int o = 16; o > 0; o >>= 1) {
            a0 += __shfl_xor_sync(0xffffffffu, a0, o);
            a1 += __shfl_xor_sync(0xffffffffu, a1, o);
        }
        if (lane == 0) { sm[RD + oc] = a0; sm[RD + 8 + oc] = a1; }
        __syncthreads();
        if (t == 0) {
            float b0 = 0.f, b1 = 0.f;
#pragma unroll
            for (int w = 0; w < 8; w++) { b0 += sm[RD + w]; b1 += sm[RD + 8 + w]; }
            out[n * 2 + 0] = b0;
            out[n * 2 + 1] = b1;
        }
    }
}

extern "C" void kernel_launch(void* const* d_in, const int* in_sizes, int n_in,
                              void* d_out, int out_size)
{
    (void)in_sizes; (void)n_in; (void)out_size;
    const float* x   = (const float*)d_in[0];
    const float* w1  = (const float*)d_in[1];
    const float* w2  = (const float*)d_in[2];
    const float* w3  = (const float*)d_in[3];
    const float* wfc = (const float*)d_in[4];
    float* outp = (float*)d_out;

    const size_t smem = TOT * sizeof(float);   // 70720 B -> 3 CTAs/SM
    cudaFuncSetAttribute(snn_fused_kernel,
                         cudaFuncAttributeMaxDynamicSharedMemorySize, (int)smem);
    snn_fused_kernel<<<1024, 256, smem>>>(x, w1, w2, w3, wfc, outp);
}

// round 6
// speedup vs baseline: 1.3078x; 1.3078x over previous
#include <cuda_runtime.h>

// SmartDoorClassifier — LIF degeneracy (alpha = exp(-200) == 0.0f in fp32):
// spiking LIF == floor(relu(.)), readout LIF == identity, time scan collapses.
// conv1(2x2,s2)->fr->pool2 -> conv2(3x3,p1)->fr->pool2 -> conv3(3x3,p1)->fr->pool2 -> FC.
// conv2/conv3: FFMA2 (fp32x2) packed along input-channel pairs; activations
// stored ic-pair-interleaved; swizzled addresses hoisted out of the ic loop.

#define SW2 0                 // 576 floats: conv2 weights packed [oc][icp][9] x float2
#define SW3 576               // 576: conv3 likewise
#define SWF 1152              // 1024 (fc weights)
#define P1  2176              // 4 icp planes x 34 rows x 48 elems x2 = 13056
#define P2  15232             // 4 x 18 x 20 x2 = 2880
#define P3  18112             // 512
#define RD  18624             // 16
#define TOT 18640             // floats -> 74560 bytes

#define RS1  96               // p1 row stride (floats) = 48 elems
#define FPS1 3264             // p1 plane stride (floats)
#define RS2  40               // p2 row stride (floats) = 20 elems
#define FPS2 720              // p2 plane stride (floats)

typedef unsigned long long u64;

__device__ __forceinline__ void fma2(u64& d, u64 a, u64 b) {
    asm("fma.rn.f32x2 %0, %1, %2, %0;" : "+l"(d) : "l"(a), "l"(b));
}
__device__ __forceinline__ void upk(u64 d, float& lo, float& hi) {
    asm("mov.b64 {%0, %1}, %2;" : "=f"(lo), "=f"(hi) : "l"(d));
}

__global__ __launch_bounds__(256, 2)
void snn_fused_kernel(const float* __restrict__ x,
                      const float* __restrict__ w1,
                      const float* __restrict__ w2,
                      const float* __restrict__ w3,
                      const float* __restrict__ wfc,
                      float* __restrict__ out)
{
    extern __shared__ float sm[];
    const int t    = threadIdx.x;
    const int n    = blockIdx.x;
    const int lane = t & 31;

    // ---- init: packed weights + zero p1/p2 (halo must be 0) -------------
    for (int i = t; i < 288; i += 256) {
        const int oc = i / 36, icp = (i % 36) / 9, q = i % 9;
        const int b = oc * 72 + icp * 18 + q;
        ((float2*)(sm + SW2))[i] = make_float2(w2[b], w2[b + 9]);
        ((float2*)(sm + SW3))[i] = make_float2(w3[b], w3[b + 9]);
    }
    for (int i = t; i < 1024; i += 256) sm[SWF + i] = wfc[i];
    {
        float4 z = make_float4(0.f, 0.f, 0.f, 0.f);
        float4* zp = (float4*)(sm + P1);
        for (int i = t; i < (13056 + 2880) / 4; i += 256) zp[i] = z;
    }

    float w1r[64];
#pragma unroll
    for (int i = 0; i < 64; i++) w1r[i] = __ldg(&w1[i]);
    __syncthreads();

    // ------------------------------------------------------------------
    // Stage A: conv1 + floor(relu) + pool2 -> p1 (icp-packed, swizzled)
    // Thread = pooled position (px=lane, py=warp+8k), computes all 8 oc.
    // ------------------------------------------------------------------
    {
        const float* xn = x + (size_t)n * 32768;
        const int px = lane, py0 = t >> 5;
#pragma unroll 1
        for (int k = 0; k < 4; k++) {
            const int py = py0 + 8 * k;
            float A0[16], A1[16];
#pragma unroll
            for (int r = 0; r < 4; r++) {
                float4 a = *(const float4*)(xn + (4 * py + r) * 128 + 4 * px);
                float4 b = *(const float4*)(xn + 16384 + (4 * py + r) * 128 + 4 * px);
                A0[r*4+0]=a.x; A0[r*4+1]=a.y; A0[r*4+2]=a.z; A0[r*4+3]=a.w;
                A1[r*4+0]=b.x; A1[r*4+1]=b.y; A1[r*4+2]=b.z; A1[r*4+3]=b.w;
            }
            float o[8];
#pragma unroll
            for (int oc = 0; oc < 8; oc++) {
                float mx = -3.0e38f;
#pragma unroll
                for (int i = 0; i < 2; i++)
#pragma unroll
                for (int j = 0; j < 2; j++) {
                    float c = 0.f;
#pragma unroll
                    for (int dy = 0; dy < 2; dy++)
#pragma unroll
                    for (int dx = 0; dx < 2; dx++) {
                        c = fmaf(A0[(2*i+dy)*4 + 2*j+dx], w1r[oc*8 +     dy*2+dx], c);
                        c = fmaf(A1[(2*i+dy)*4 + 2*j+dx], w1r[oc*8 + 4 + dy*2+dx], c);
                    }
                    mx = fmaxf(mx, c);
                }
                o[oc] = floorf(fmaxf(mx, 0.f));
            }
            const int row = py + 1, col = px + 1;
            const int key = (row >> 1) & 7;
            const int chunk = col >> 1;
            const int phys = (chunk & ~7) | ((chunk & 7) ^ key);
            const int eoff = row * RS1 + (phys * 2 + (col & 1)) * 2;
#pragma unroll
            for (int icp = 0; icp < 4; icp++)
                *(float2*)(sm + P1 + icp * FPS1 + eoff) = make_float2(o[2*icp], o[2*icp+1]);
        }
    }
    __syncthreads();

    // ------------------------------------------------------------------
    // Stage B: conv2 + floor(relu) + pool2 -> p2 (icp-packed)
    // warp = oc; lane = half*16 + py2 (R3-verified mapping). Two 4-pooled-col
    // passes; window start chunk c0 = 8*half + 4*g (chunk = 2 elems = 16B).
    // Swizzled addresses hoisted out of the icp loop (pure LDS+FFMA2 inner).
    // ------------------------------------------------------------------
    {
        const int oc  = t >> 5;
        const int py2 = lane & 15, half = lane >> 4;
        const float* wb = sm + SW2 + oc * 72;
        const int row2 = py2 + 1;
        const int key2 = (row2 >> 1) & 1;
#pragma unroll 1
        for (int g = 0; g < 2; g++) {
            const int c0 = 8 * half + 4 * g;     // window start chunk
            int off[4][5];                       // float indices into sm (icp 0)
#pragma unroll
            for (int r = 0; r < 4; r++) {
                const int row = 2 * py2 + r;
                const int key = (row >> 1) & 7;
                const int rbase = P1 + row * RS1;
#pragma unroll
                for (int k = 0; k < 5; k++) {
                    const int c = c0 + k;
                    off[r][k] = rbase + ((c & ~7) | ((c & 7) ^ key)) * 4;
                }
            }
            u64 acc[16];                         // [jp][cell(i*2+jj)]
#pragma unroll
            for (int i = 0; i < 16; i++) acc[i] = 0ull;
#pragma unroll
            for (int icp = 0; icp < 4; icp++) {
                u64 w[9];
#pragma unroll
                for (int q = 0; q < 9; q++)
                    w[q] = *(const u64*)(wb + (icp * 9 + q) * 2);
#pragma unroll
                for (int r = 0; r < 4; r++) {
                    u64 e[10];
#pragma unroll
                    for (int k = 0; k < 5; k++) {
                        ulonglong2 v = *(const ulonglong2*)(sm + off[r][k] + icp * FPS1);
                        e[2*k] = v.x; e[2*k+1] = v.y;
                    }
#pragma unroll
                    for (int ky = 0; ky < 3; ky++) {
                        const int i = r - ky;
                        if (i >= 0 && i <= 1) {
#pragma unroll
                            for (int jp = 0; jp < 4; jp++)
#pragma unroll
                            for (int jj = 0; jj < 2; jj++)
#pragma unroll
                            for (int kx = 0; kx < 3; kx++)
                                fma2(acc[jp*4 + i*2 + jj], e[2*jp + jj + kx], w[ky*3 + kx]);
                        }
                    }
                }
            }
            // epilogue: sum ic halves, pool, floor(relu), store (oc-parity packed)
#pragma unroll
            for (int jp = 0; jp < 4; jp++) {
                float s[4];
#pragma unroll
                for (int c = 0; c < 4; c++) {
                    float lo, hi; upk(acc[jp*4 + c], lo, hi); s[c] = lo + hi;
                }
                float mx = fmaxf(fmaxf(s[0], s[1]), fmaxf(s[2], s[3]));
                const int px2 = half * 8 + g * 4 + jp;
                const int e2 = px2 + 1;
                const int pe = (((e2 >> 1) ^ key2) << 1) | (e2 & 1);
                sm[P2 + (oc >> 1) * FPS2 + row2 * RS2 + pe * 2 + (oc & 1)]
                    = floorf(fmaxf(mx, 0.f));
            }
        }
    }
    __syncthreads();

    // ------------------------------------------------------------------
    // Stage C: conv3 + floor(relu) + pool2 -> p3[8][8][8]
    // warp = oc; lane = py3*4 + q (cols 2q, 2q+1). Addresses hoisted.
    // ------------------------------------------------------------------
    {
        const int oc  = t >> 5;
        const int py3 = lane >> 2, q = lane & 3;
        const float* wb = sm + SW3 + oc * 72;
        int off3[4][3];
#pragma unroll
        for (int r = 0; r < 4; r++) {
            const int row = 2 * py3 + r;
            const int key = (row >> 1) & 1;
#pragma unroll
            for (int k = 0; k < 3; k++)
                off3[r][k] = P2 + row * RS2 + ((2 * q + k) ^ key) * 4;
        }
        u64 acc[8];   // [j][cell]
#pragma unroll
        for (int i = 0; i < 8; i++) acc[i] = 0ull;
#pragma unroll
        for (int icp = 0; icp < 4; icp++) {
            u64 w[9];
#pragma unroll
            for (int p = 0; p < 9; p++)
                w[p] = *(const u64*)(wb + (icp * 9 + p) * 2);
#pragma unroll
            for (int r = 0; r < 4; r++) {
                u64 e[6];
#pragma unroll
                for (int k = 0; k < 3; k++) {
                    ulonglong2 v = *(const ulonglong2*)(sm + off3[r][k] + icp * FPS2);
                    e[2*k] = v.x; e[2*k+1] = v.y;
                }
#pragma unroll
                for (int ky = 0; ky < 3; ky++) {
                    const int i = r - ky;
                    if (i >= 0 && i <= 1) {
#pragma unroll
                        for (int j = 0; j < 2; j++)
#pragma unroll
                        for (int jj = 0; jj < 2; jj++)
#pragma unroll
                        for (int kx = 0; kx < 3; kx++)
                            fma2(acc[j*4 + i*2 + jj], e[2*j + jj + kx], w[ky*3 + kx]);
                    }
                }
            }
        }
#pragma unroll
        for (int j = 0; j < 2; j++) {
            float s[4];
#pragma unroll
            for (int c = 0; c < 4; c++) {
                float lo, hi; upk(acc[j*4 + c], lo, hi); s[c] = lo + hi;
            }
            float mx = fmaxf(fmaxf(s[0], s[1]), fmaxf(s[2], s[3]));
            sm[P3 + oc * 64 + py3 * 8 + 2 * q + j] = floorf(fmaxf(mx, 0.f));
        }
    }
    __syncthreads();

    // ------------------------------------------------------------------
    // Stage D: FC 512 -> 2 (readout LIF = identity)
    // ------------------------------------------------------------------
    {
        const int oc = t >> 5;
        float a0 = 0.f, a1 = 0.f;
        for (int i = t; i < 512; i += 256) {
            const float v = sm[P3 + i];
            a0 = fmaf(v, sm[SWF + i],       a0);
            a1 = fmaf(v, sm[SWF + 512 + i], a1);
        }
#pragma unroll
        for (int o = 16; o > 0; o >>= 1) {
            a0 += __shfl_xor_sync(0xffffffffu, a0, o);
            a1 += __shfl_xor_sync(0xffffffffu, a1, o);
        }
        if (lane == 0) { sm[RD + oc] = a0; sm[RD + 8 + oc] = a1; }
        __syncthreads();
        if (t == 0) {
            float b0 = 0.f, b1 = 0.f;
#pragma unroll
            for (int w = 0; w < 8; w++) { b0 += sm[RD + w]; b1 += sm[RD + 8 + w]; }
            out[n * 2 + 0] = b0;
            out[n * 2 + 1] = b1;
        }
    }
}

extern "C" void kernel_launch(void* const* d_in, const int* in_sizes, int n_in,
                              void* d_out, int out_size)
{
    (void)in_sizes; (void)n_in; (void)out_size;
    const float* x   = (const float*)d_in[0];
    const float* w1  = (const float*)d_in[1];
    const float* w2  = (const float*)d_in[2];
    const float* w3  = (const float*)d_in[3];
    const float* wfc = (const float*)d_in[4];
    float* outp = (float*)d_out;

    const size_t smem = TOT * sizeof(float);   // 74560 B
    cudaFuncSetAttribute(snn_fused_kernel,
                         cudaFuncAttributeMaxDynamicSharedMemorySize, (int)smem);
    snn_fused_kernel<<<1024, 256, smem>>>(x, w1, w2, w3, wfc, outp);
}